// round 12
// baseline (speedup 1.0000x reference)
#include <cuda_runtime.h>
#include <cuda_bf16.h>
#include <cstdint>
#include <cmath>

// ---------------------------------------------------------------------------
// Problem shapes
//   B=32, T=256, IN=64, D=128
// Outputs (fp32, concatenated):
//   h_final (32,128)            @ 0          size 4096
//   y       (32,256,128)        @ 4096       size 1048576
//   jacs    (256,32,128,128)    @ 1052672    size 134217728
//   dh_dWh  (32,128,128,128)    @ 135270400  size 67108864
//
// Correctness model (validated R11, passed): output 3 is the fp32 residue
// pattern of h_final-1; it requires g = fl(1 / fl(1 + fl(exp(-sg)))) with a
// correctly-rounded-in-double exp, serial ascending-k fma dots, XLA chlo erf
// gelu, and the literal two-step update fl(fl(g*h)+fl(1-g)).
//
// R12 perf changes (numerics preserved):
//   * exp(double) libm -> inline degree-14 Taylor in double (Estrin).
//     |poly err| ~1e-15 rel for |x|<=0.5; float rounding identical to
//     float(exp(double)) except w.p. ~1e-8/eval. |x|>0.5 falls back to libm.
//     Cuts the per-step serial critical path by ~1500+ cycles.
//   * jac_gemm __launch_bounds__(256,2): 2 CTAs/SM (occupancy 23%->47%).
// ---------------------------------------------------------------------------

#define Bsz 32
#define Tsz 256
#define INsz 64
#define Dsz 128
#define BT (Bsz*Tsz)           // 8192
#define NN (Dsz*Dsz)           // 16384

// ------------------------- scratch (static device) -------------------------
__device__ float          d_xw[BT*Dsz];          // x @ Wx, layout [(b*T+t)*128+i]
__device__ __nv_bfloat16  d_gp[BT*Dsz];          // gelu'(pre), layout [(t*B+b)*128+k]
__device__ float          d_g [BT*Dsz];          // gate,  layout [(t*B+b)*128+i]
__device__ float          d_c [BT*Dsz];          // (h-1)g(1-g), same layout
__device__ __nv_bfloat16  d_vt[NN*Dsz];          // Vt[(i*128+j)][k] = Wgate[k,i]*Wh[j,k]
__device__ float          d_cf[Bsz*Dsz];
__device__ float          d_gpf[Bsz*Dsz];

__device__ __forceinline__ uint32_t smem_u32(const void* p) {
    uint32_t a;
    asm("{ .reg .u64 t; cvta.to.shared.u64 t, %1; cvt.u32.u64 %0, t; }" : "=r"(a) : "l"(p));
    return a;
}

// ------------------------- reference-exact transcendentals -----------------
// XLA chlo erf f32: erf(x) = x * P(x^2) / Q(x^2), x clamped to [-4, 4].
__device__ __forceinline__ float xla_erf(float x) {
    float xc = fminf(fmaxf(x, -4.0f), 4.0f);
    float x2 = __fmul_rn(xc, xc);
    float p = -2.72614225801306e-10f;
    p = __fmaf_rn(p, x2,  2.77068142495902e-08f);
    p = __fmaf_rn(p, x2, -2.10102402082508e-06f);
    p = __fmaf_rn(p, x2, -5.69250639462346e-05f);
    p = __fmaf_rn(p, x2, -7.34990630326855e-04f);
    p = __fmaf_rn(p, x2, -2.95459980854025e-03f);
    p = __fmaf_rn(p, x2, -1.60960333262415e-02f);
    float num = __fmul_rn(xc, p);
    float q = -1.45660718464996e-05f;
    q = __fmaf_rn(q, x2, -2.13374055278905e-04f);
    q = __fmaf_rn(q, x2, -1.68282697438203e-03f);
    q = __fmaf_rn(q, x2, -7.37332916720468e-03f);
    q = __fmaf_rn(q, x2, -1.42647390514189e-02f);
    return __fdiv_rn(num, q);
}

// Near-correctly-rounded expf: degree-14 Taylor in double for |x|<=0.5
// (truncation ~7e-16 rel, well under the float-rounding decision threshold),
// Estrin-scheduled to cut FP64 dependency depth. Fallback to libm exp for
// the (rare) |x|>0.5. Float result matches float(exp(double)) essentially
// always, preserving the R11-validated g bits.
__device__ __forceinline__ float cr_expf(float xf) {
    double x = (double)xf;
    if (fabs(x) > 0.5) return (float)exp(x);
    const double C2  = 5.0000000000000000e-01,  C3  = 1.6666666666666666e-01;
    const double C4  = 4.1666666666666664e-02,  C5  = 8.3333333333333332e-03;
    const double C6  = 1.3888888888888889e-03,  C7  = 1.9841269841269841e-04;
    const double C8  = 2.4801587301587302e-05,  C9  = 2.7557319223985893e-06;
    const double C10 = 2.7557319223985888e-07,  C11 = 2.5052108385441720e-08;
    const double C12 = 2.0876756987868100e-09,  C13 = 1.6059043836821613e-10;
    const double C14 = 1.1470745597729725e-11;
    double x2 = x * x;
    double x4 = x2 * x2;
    double x8 = x4 * x4;
    double b0 = fma(fma(C3,  x, C2),  x2, x + 1.0);
    double b1 = fma(fma(C7,  x, C6),  x2, fma(C5,  x, C4));
    double b2 = fma(fma(C11, x, C10), x2, fma(C9,  x, C8));
    double b3 = fma(C14, x2, fma(C13, x, C12));
    double r  = fma(fma(b3, x4, b2), x8, fma(b1, x4, b0));
    return (float)r;
}

// Direct-form logistic: g = fl(1 / fl(1 + fl(exp(-x))))
__device__ __forceinline__ float ref_logistic(float x) {
    float e = cr_expf(-x);
    float d = __fadd_rn(1.0f, e);
    return __fdiv_rn(1.0f, d);
}

// jax.nn.gelu exact: x * (erf(x / sqrt(2)) + 1) / 2
#define SQRT2_F32 1.41421356237309504880f
__device__ __forceinline__ float xla_gelu(float x, float* erf_out) {
    float u = __fdiv_rn(x, SQRT2_F32);
    float e = xla_erf(u);
    *erf_out = e;
    float s = __fadd_rn(e, 1.0f);
    float m = __fmul_rn(x, s);
    return __fmul_rn(m, 0.5f);      // /2 == *0.5 bitwise
}

// ------------------------- K0: xw = x @ Wx ---------------------------------
__global__ void xw_kernel(const float* __restrict__ x, const float* __restrict__ Wx) {
    __shared__ __align__(16) float xs[INsz];
    int bt = blockIdx.x;
    int i  = threadIdx.x;
    if (i < INsz) xs[i] = x[(size_t)bt * INsz + i];
    __syncthreads();
    float acc = 0.f;
#pragma unroll
    for (int k = 0; k < INsz; k++) acc = __fmaf_rn(xs[k], Wx[k * Dsz + i], acc);
    d_xw[(size_t)bt * Dsz + i] = acc;
}

// ------------------------- K0b: build Vt -----------------------------------
// Vt[n][k] = Wgate[k][i] * Wh[j][k],  n = i*128 + j
__global__ void build_vt_kernel(const float* __restrict__ Wh, const float* __restrict__ Wgate) {
    int n = blockIdx.x;
    int k = threadIdx.x;
    int i = n >> 7, j = n & 127;
    d_vt[(size_t)n * Dsz + k] = __float2bfloat16(Wgate[k * Dsz + i] * Wh[j * Dsz + k]);
}

// ------------------------- K1: the recurrence (bit-exact, 2 batches/CTA) ---
// 16 CTAs x 256 threads. tid = i + 128*s; batch b = blockIdx.x*2 + s.
#define WG_PITCH 132

__global__ __launch_bounds__(256, 1) void rnn_kernel(
    const float* __restrict__ h0, const float* __restrict__ Wh,
    const float* __restrict__ Wgate, float* __restrict__ y, float* __restrict__ hfin) {
    extern __shared__ __align__(16) float dsm[];
    float* wgT  = dsm;                          // [128][WG_PITCH], shared by both batches
    float* h_sh = dsm + 128 * WG_PITCH;         // [2][128]
    float* a_sh = h_sh + 256;                   // [2][128]

    int tid = threadIdx.x;
    int i   = tid & 127;
    int s   = tid >> 7;
    int b   = blockIdx.x * 2 + s;

    // Wh column i -> registers (ascending k); same for both halves.
    float wh[128];
#pragma unroll
    for (int k = 0; k < 128; k++) wh[k] = Wh[k * Dsz + i];

    // Wgate column i -> contiguous smem row i (batch-independent; s==0 fills)
    if (s == 0)
        for (int k = 0; k < 128; k++) wgT[i * WG_PITCH + k] = Wgate[k * Dsz + i];

    h_sh[s * 128 + i] = h0[b * Dsz + i];
    __syncthreads();

    const float* xwp = d_xw + (size_t)b * Tsz * Dsz;
    float* yp        = y + (size_t)b * Tsz * Dsz;
    float* hrow      = &h_sh[s * 128];
    float* arow      = &a_sh[s * 128];

    for (int t = 0; t < Tsz; t++) {
        // ---- pre_i = fl(xw_i + serial_fma_k(h_k * Wh[k,i])) ----
        float acc = 0.f;
#pragma unroll
        for (int k = 0; k < 128; k += 4) {
            float4 hv = *(const float4*)&hrow[k];
            acc = __fmaf_rn(hv.x, wh[k + 0], acc);
            acc = __fmaf_rn(hv.y, wh[k + 1], acc);
            acc = __fmaf_rn(hv.z, wh[k + 2], acc);
            acc = __fmaf_rn(hv.w, wh[k + 3], acc);
        }
        float pre = __fadd_rn(xwp[t * Dsz + i], acc);

        // ---- a = gelu(pre) (XLA-exact), gp = gelu'(pre) (loose, bf16 out) --
        float e;
        float a = xla_gelu(pre, &e);
        arow[i] = a;
        {
            float ph = 0.5f * (1.0f + e);
            float gp = ph + pre * 0.39894228040143268f * __expf(-0.5f * pre * pre);
            d_gp[((size_t)t * Bsz + b) * Dsz + i] = __float2bfloat16(gp);
        }
        __syncthreads();    // a ready; all phase-A h reads complete

        // ---- sg_i = serial_fma_k(a_k * Wgate[k,i]) ----
        float acc2 = 0.f;
        const float* wgr = &wgT[i * WG_PITCH];
#pragma unroll
        for (int k = 0; k < 128; k += 4) {
            float4 av = *(const float4*)&arow[k];
            float4 wv = *(const float4*)&wgr[k];
            acc2 = __fmaf_rn(av.x, wv.x, acc2);
            acc2 = __fmaf_rn(av.y, wv.y, acc2);
            acc2 = __fmaf_rn(av.z, wv.z, acc2);
            acc2 = __fmaf_rn(av.w, wv.w, acc2);
        }

        // ---- g = logistic(sg)  (DIRECT exp form, inline CR exp) ----
        float g = ref_logistic(acc2);

        // ---- h' = fl(fl(g*h) + fl(1-g))  (literal jax form) ----
        float hold = hrow[i];
        float t1 = __fmul_rn(g, hold);
        float t2 = __fsub_rn(1.0f, g);
        float hnew = __fadd_rn(t1, t2);

        size_t r = ((size_t)t * Bsz + b) * Dsz + i;
        float hm1 = __fsub_rn(hold, 1.0f);
        d_g[r] = g;
        d_c[r] = hm1 * g * (1.0f - g);
        yp[t * Dsz + i] = hnew;
        hrow[i] = hnew;
        if (t == Tsz - 1) hfin[b * Dsz + i] = hnew;
        __syncthreads();    // h stable for next step
    }
}

// ------------------------- K2: jac GEMM (mma.sync bf16) --------------------
// D[m][n] = sum_k GP[tileM*128+m][k] * Vt[tileN*128+n][k]   (NT gemm)
// jac[tb][i=tileN][j] = g*delta(tileN,j) + c * D
#define K2_LDS 136              // smem row stride in elements (128 + 8 pad)

__global__ __launch_bounds__(256, 2) void jac_gemm_kernel(float* __restrict__ jac_out) {
    extern __shared__ __align__(16) __nv_bfloat16 sm[];
    __nv_bfloat16* As = sm;                       // 128 x K2_LDS
    __nv_bfloat16* Bs = sm + 128 * K2_LDS;        // 128 x K2_LDS

    const int tid   = threadIdx.x;
    const int lane  = tid & 31;
    const int wid   = tid >> 5;
    const int wm    = wid & 1;                    // 0..1  (M dir, 64 rows each)
    const int wn    = wid >> 1;                   // 0..3  (N dir, 32 cols each)
    const int tileN = blockIdx.x;                 // i   (0..127)
    const int tileM = blockIdx.y;                 // tb/128 (0..63)

    const uint4* gA = (const uint4*)(d_gp + (size_t)tileM * 128 * Dsz);
    const uint4* gB = (const uint4*)(d_vt + (size_t)tileN * 128 * Dsz);
#pragma unroll
    for (int it = 0; it < 8; it++) {
        int idx   = tid + it * 256;               // 0..2047
        int row   = idx >> 4;
        int chunk = idx & 15;
        *(uint4*)&As[row * K2_LDS + chunk * 8] = gA[idx];
        *(uint4*)&Bs[row * K2_LDS + chunk * 8] = gB[idx];
    }
    __syncthreads();

    const uint32_t as_b = smem_u32(As);
    const uint32_t bs_b = smem_u32(Bs);

    float acc[4][4][4];
#pragma unroll
    for (int mf = 0; mf < 4; mf++)
#pragma unroll
        for (int nf = 0; nf < 4; nf++)
#pragma unroll
            for (int r = 0; r < 4; r++) acc[mf][nf][r] = 0.f;

    const int RM = wm * 64;
    const int CN = wn * 32;

#pragma unroll
    for (int kk = 0; kk < 8; kk++) {
        const int k0 = kk * 16;
        uint32_t a[4][4];
#pragma unroll
        for (int mf = 0; mf < 4; mf++) {
            uint32_t addr = as_b +
                (uint32_t)(((RM + mf * 16 + (lane & 15)) * K2_LDS + k0 + ((lane >> 4) << 3)) * 2);
            asm volatile("ldmatrix.sync.aligned.m8n8.x4.shared.b16 {%0,%1,%2,%3}, [%4];"
                : "=r"(a[mf][0]), "=r"(a[mf][1]), "=r"(a[mf][2]), "=r"(a[mf][3]) : "r"(addr));
        }
        uint32_t bfr[4][2];
#pragma unroll
        for (int nh = 0; nh < 2; nh++) {
            int tile = lane >> 3;
            int rr   = CN + nh * 16 + (lane & 7) + (tile >> 1) * 8;
            int cc   = k0 + (tile & 1) * 8;
            uint32_t addr = bs_b + (uint32_t)((rr * K2_LDS + cc) * 2);
            asm volatile("ldmatrix.sync.aligned.m8n8.x4.shared.b16 {%0,%1,%2,%3}, [%4];"
                : "=r"(bfr[2 * nh][0]), "=r"(bfr[2 * nh][1]),
                  "=r"(bfr[2 * nh + 1][0]), "=r"(bfr[2 * nh + 1][1]) : "r"(addr));
        }
#pragma unroll
        for (int mf = 0; mf < 4; mf++)
#pragma unroll
            for (int nf = 0; nf < 4; nf++) {
                asm volatile(
                    "mma.sync.aligned.m16n8k16.row.col.f32.bf16.bf16.f32 "
                    "{%0,%1,%2,%3}, {%4,%5,%6,%7}, {%8,%9}, {%0,%1,%2,%3};"
                    : "+f"(acc[mf][nf][0]), "+f"(acc[mf][nf][1]),
                      "+f"(acc[mf][nf][2]), "+f"(acc[mf][nf][3])
                    : "r"(a[mf][0]), "r"(a[mf][1]), "r"(a[mf][2]), "r"(a[mf][3]),
                      "r"(bfr[nf][0]), "r"(bfr[nf][1]));
            }
    }

    const int r0 = lane >> 2;            // 0..7
    const int c0 = (lane & 3) * 2;       // 0,2,4,6
#pragma unroll
    for (int mf = 0; mf < 4; mf++) {
        size_t tb0 = (size_t)tileM * 128 + RM + mf * 16 + r0;       // rows r0, r0+8
        float cc0 = d_c[tb0 * Dsz + tileN];
        float gg0 = d_g[tb0 * Dsz + tileN];
        float cc1 = d_c[(tb0 + 8) * Dsz + tileN];
        float gg1 = d_g[(tb0 + 8) * Dsz + tileN];
        float* p0 = jac_out + (tb0 * Dsz + tileN) * Dsz;
        float* p1 = jac_out + ((tb0 + 8) * Dsz + tileN) * Dsz;
#pragma unroll
        for (int nf = 0; nf < 4; nf++) {
            int j = CN + nf * 8 + c0;
            float2 v0, v1;
            v0.x = cc0 * acc[mf][nf][0];
            v0.y = cc0 * acc[mf][nf][1];
            v1.x = cc1 * acc[mf][nf][2];
            v1.y = cc1 * acc[mf][nf][3];
            if (j == tileN)     { v0.x += gg0; v1.x += gg1; }
            if (j + 1 == tileN) { v0.y += gg0; v1.y += gg1; }
            *(float2*)(p0 + j) = v0;
            *(float2*)(p1 + j) = v1;
        }
    }
}

// ------------------------- K3a: final-step recompute -----------------------
__global__ void final_step_kernel(const float* __restrict__ Wh,
                                  const float* __restrict__ Wgate,
                                  const float* __restrict__ hfin) {
    __shared__ __align__(16) float hs[Dsz];
    __shared__ __align__(16) float as_[Dsz];
    int b = blockIdx.x, i = threadIdx.x;
    hs[i] = hfin[b * Dsz + i];
    __syncthreads();
    float acc = 0.f;
#pragma unroll
    for (int j = 0; j < Dsz; j++) acc = __fmaf_rn(hs[j], Wh[j * Dsz + i], acc);
    float pre = __fadd_rn(d_xw[((size_t)b * Tsz + (Tsz - 1)) * Dsz + i], acc);
    float e;
    float a = xla_gelu(pre, &e);
    float ph = 0.5f * (1.0f + e);
    d_gpf[b * Dsz + i] = ph + pre * 0.39894228040143268f * __expf(-0.5f * pre * pre);
    as_[i] = a;
    __syncthreads();
    float sg = 0.f;
#pragma unroll
    for (int k = 0; k < Dsz; k++) sg = __fmaf_rn(as_[k], Wgate[k * Dsz + i], sg);
    float g = ref_logistic(sg);
    d_cf[b * Dsz + i] = __fsub_rn(hs[i], 1.0f) * g * (1.0f - g);
}

// ------------------------- K3b: dh_dWh -------------------------------------
// dwh[b,i,p,q] = cf[b,i] * hf[b,p] * gpf[b,q] * Wgate[q,i]
__global__ void dwh_kernel(const float* __restrict__ Wgate,
                           const float* __restrict__ hfin,
                           float* __restrict__ dwh) {
    __shared__ __align__(16) float hs[Dsz];
    int i = blockIdx.x, b = blockIdx.y, q = threadIdx.x;
    float w = Wgate[q * Dsz + i] * d_gpf[b * Dsz + q];
    hs[q] = hfin[b * Dsz + q];
    float cw = d_cf[(size_t)b * Dsz + i] * w;
    __syncthreads();
    float* op = dwh + ((size_t)b * Dsz + i) * Dsz * Dsz + q;
#pragma unroll 4
    for (int p = 0; p < Dsz; p++) op[(size_t)p * Dsz] = cw * hs[p];
}

// ------------------------- launch ------------------------------------------
extern "C" void kernel_launch(void* const* d_in, const int* in_sizes, int n_in,
                              void* d_out, int out_size) {
    const float* x     = (const float*)d_in[0];
    const float* h0    = (const float*)d_in[1];
    const float* Wx    = (const float*)d_in[2];
    const float* Wgate = (const float*)d_in[3];
    const float* Wh    = (const float*)d_in[4];

    float* out  = (float*)d_out;
    float* hfin = out;                                   // 4096
    float* y    = out + 4096;                            // 1,048,576
    float* jac  = out + 4096 + (size_t)Bsz * Tsz * Dsz;  // 134,217,728
    float* dwh  = jac + (size_t)Tsz * Bsz * Dsz * Dsz;   // 67,108,864

    const int K2_SMEM  = 2 * 128 * K2_LDS * 2;           // 69632 B
    const int K1_SMEM  = (128 * WG_PITCH + 512) * 4;     // 69632 B
    cudaFuncSetAttribute(jac_gemm_kernel,
                         cudaFuncAttributeMaxDynamicSharedMemorySize, K2_SMEM);
    cudaFuncSetAttribute(rnn_kernel,
                         cudaFuncAttributeMaxDynamicSharedMemorySize, K1_SMEM);

    xw_kernel<<<BT, Dsz>>>(x, Wx);
    build_vt_kernel<<<NN, Dsz>>>(Wh, Wgate);
    rnn_kernel<<<Bsz / 2, 256, K1_SMEM>>>(h0, Wh, Wgate, y, hfin);
    jac_gemm_kernel<<<dim3(Dsz, BT / 128), 256, K2_SMEM>>>(jac);
    final_step_kernel<<<Bsz, Dsz>>>(Wh, Wgate, hfin);
    dwh_kernel<<<dim3(Dsz, Bsz), Dsz>>>(Wgate, hfin, dwh);
}

// round 17
// speedup vs baseline: 1.4741x; 1.4741x over previous
#include <cuda_runtime.h>
#include <cuda_bf16.h>
#include <cstdint>
#include <cmath>

// ---------------------------------------------------------------------------
// Problem shapes
//   B=32, T=256, IN=64, D=128
// Outputs (fp32, concatenated):
//   h_final (32,128)            @ 0          size 4096
//   y       (32,256,128)        @ 4096       size 1048576
//   jacs    (256,32,128,128)    @ 1052672    size 134217728
//   dh_dWh  (32,128,128,128)    @ 135270400  size 67108864
//
// Correctness model (validated R11): g = fl(1/fl(1+fl(exp(-sg)))) with a
// correctly-rounded-in-double exp, serial ascending-k fma dots, XLA chlo erf
// gelu, literal two-step update fl(fl(g*h)+fl(1-g)).
//
// R13 perf change: K1 restructured as warp-specialized ping-pong.
//   R12 ncu+arithmetic showed K1 (~620us) was bound by smem crossbar traffic
//   in dot2 (per-thread Wgate rows: 128KB/step/CTA, 4-way bank conflicts,
//   ~4000 cyc/step). Now: half A (threads 0-127) holds Wh[:,i] in registers
//   and computes dot1+gelu; half B (threads 128-255) holds Wgate[:,i] in
//   registers and computes dot2+logistic+update. All smem reads are warp
//   broadcasts. Per-(b,i) arithmetic sequence is BIT-IDENTICAL to R11/R12.
// ---------------------------------------------------------------------------

#define Bsz 32
#define Tsz 256
#define INsz 64
#define Dsz 128
#define BT (Bsz*Tsz)           // 8192
#define NN (Dsz*Dsz)           // 16384

// ------------------------- scratch (static device) -------------------------
__device__ float          d_xw[BT*Dsz];          // x @ Wx, layout [(b*T+t)*128+i]
__device__ __nv_bfloat16  d_gp[BT*Dsz];          // gelu'(pre), layout [(t*B+b)*128+k]
__device__ float          d_g [BT*Dsz];          // gate,  layout [(t*B+b)*128+i]
__device__ float          d_c [BT*Dsz];          // (h-1)g(1-g), same layout
__device__ __nv_bfloat16  d_vt[NN*Dsz];          // Vt[(i*128+j)][k] = Wgate[k,i]*Wh[j,k]
__device__ float          d_cf[Bsz*Dsz];
__device__ float          d_gpf[Bsz*Dsz];

__device__ __forceinline__ uint32_t smem_u32(const void* p) {
    uint32_t a;
    asm("{ .reg .u64 t; cvta.to.shared.u64 t, %1; cvt.u32.u64 %0, t; }" : "=r"(a) : "l"(p));
    return a;
}

// ------------------------- reference-exact transcendentals -----------------
// XLA chlo erf f32: erf(x) = x * P(x^2) / Q(x^2), x clamped to [-4, 4].
__device__ __forceinline__ float xla_erf(float x) {
    float xc = fminf(fmaxf(x, -4.0f), 4.0f);
    float x2 = __fmul_rn(xc, xc);
    float p = -2.72614225801306e-10f;
    p = __fmaf_rn(p, x2,  2.77068142495902e-08f);
    p = __fmaf_rn(p, x2, -2.10102402082508e-06f);
    p = __fmaf_rn(p, x2, -5.69250639462346e-05f);
    p = __fmaf_rn(p, x2, -7.34990630326855e-04f);
    p = __fmaf_rn(p, x2, -2.95459980854025e-03f);
    p = __fmaf_rn(p, x2, -1.60960333262415e-02f);
    float num = __fmul_rn(xc, p);
    float q = -1.45660718464996e-05f;
    q = __fmaf_rn(q, x2, -2.13374055278905e-04f);
    q = __fmaf_rn(q, x2, -1.68282697438203e-03f);
    q = __fmaf_rn(q, x2, -7.37332916720468e-03f);
    q = __fmaf_rn(q, x2, -1.42647390514189e-02f);
    return __fdiv_rn(num, q);
}

// Near-correctly-rounded expf: degree-14 Taylor in double for |x|<=0.5
// (truncation ~7e-16 rel), Estrin-scheduled. Fallback to libm for |x|>0.5.
// Matches float(exp(double)) essentially always (R11-validated g bits).
__device__ __forceinline__ float cr_expf(float xf) {
    double x = (double)xf;
    if (fabs(x) > 0.5) return (float)exp(x);
    const double C2  = 5.0000000000000000e-01,  C3  = 1.6666666666666666e-01;
    const double C4  = 4.1666666666666664e-02,  C5  = 8.3333333333333332e-03;
    const double C6  = 1.3888888888888889e-03,  C7  = 1.9841269841269841e-04;
    const double C8  = 2.4801587301587302e-05,  C9  = 2.7557319223985893e-06;
    const double C10 = 2.7557319223985888e-07,  C11 = 2.5052108385441720e-08;
    const double C12 = 2.0876756987868100e-09,  C13 = 1.6059043836821613e-10;
    const double C14 = 1.1470745597729725e-11;
    double x2 = x * x;
    double x4 = x2 * x2;
    double x8 = x4 * x4;
    double b0 = fma(fma(C3,  x, C2),  x2, x + 1.0);
    double b1 = fma(fma(C7,  x, C6),  x2, fma(C5,  x, C4));
    double b2 = fma(fma(C11, x, C10), x2, fma(C9,  x, C8));
    double b3 = fma(C14, x2, fma(C13, x, C12));
    double r  = fma(fma(b3, x4, b2), x8, fma(b1, x4, b0));
    return (float)r;
}

// Direct-form logistic: g = fl(1 / fl(1 + fl(exp(-x))))
__device__ __forceinline__ float ref_logistic(float x) {
    float e = cr_expf(-x);
    float d = __fadd_rn(1.0f, e);
    return __fdiv_rn(1.0f, d);
}

// jax.nn.gelu exact: x * (erf(x / sqrt(2)) + 1) / 2
#define SQRT2_F32 1.41421356237309504880f
__device__ __forceinline__ float xla_gelu(float x, float* erf_out) {
    float u = __fdiv_rn(x, SQRT2_F32);
    float e = xla_erf(u);
    *erf_out = e;
    float s = __fadd_rn(e, 1.0f);
    float m = __fmul_rn(x, s);
    return __fmul_rn(m, 0.5f);      // /2 == *0.5 bitwise
}

// ------------------------- K0: xw = x @ Wx ---------------------------------
__global__ void xw_kernel(const float* __restrict__ x, const float* __restrict__ Wx) {
    __shared__ __align__(16) float xs[INsz];
    int bt = blockIdx.x;
    int i  = threadIdx.x;
    if (i < INsz) xs[i] = x[(size_t)bt * INsz + i];
    __syncthreads();
    float acc = 0.f;
#pragma unroll
    for (int k = 0; k < INsz; k++) acc = __fmaf_rn(xs[k], Wx[k * Dsz + i], acc);
    d_xw[(size_t)bt * Dsz + i] = acc;
}

// ------------------------- K0b: build Vt -----------------------------------
// Vt[n][k] = Wgate[k][i] * Wh[j][k],  n = i*128 + j
__global__ void build_vt_kernel(const float* __restrict__ Wh, const float* __restrict__ Wgate) {
    int n = blockIdx.x;
    int k = threadIdx.x;
    int i = n >> 7, j = n & 127;
    d_vt[(size_t)n * Dsz + k] = __float2bfloat16(Wgate[k * Dsz + i] * Wh[j * Dsz + k]);
}

// ------------------------- K1: recurrence, warp-specialized ping-pong ------
// 32 CTAs (one per batch) x 256 threads.
//   half A = threads 0..127   : Wh column i in regs; dot1 + gelu -> a_sh
//   half B = threads 128..255 : Wgate column i in regs; dot2 + logistic + h
// All smem reads are warp-uniform broadcasts (no crossbar pressure).
__global__ __launch_bounds__(256, 1) void rnn_kernel(
    const float* __restrict__ h0, const float* __restrict__ Wh,
    const float* __restrict__ Wgate, float* __restrict__ y, float* __restrict__ hfin) {
    __shared__ __align__(16) float h_sh[Dsz];
    __shared__ __align__(16) float a_sh[Dsz];

    const int tid = threadIdx.x;
    const int i   = tid & 127;
    const bool isA = tid < 128;
    const int b   = blockIdx.x;

    // Each half loads its own weight column (ascending k), into registers.
    float wreg[128];
    {
        const float* W = isA ? Wh : Wgate;
#pragma unroll
        for (int k = 0; k < 128; k++) wreg[k] = W[k * Dsz + i];
    }

    if (isA) h_sh[i] = h0[b * Dsz + i];
    __syncthreads();

    const float* xwp = d_xw + (size_t)b * Tsz * Dsz;
    float* yp        = y + (size_t)b * Tsz * Dsz;

    float xw_cur = isA ? xwp[i] : 0.f;   // prefetched xw for t=0 (half A only)

    for (int t = 0; t < Tsz; t++) {
        if (isA) {
            // ---- pre_i = fl(xw_i + serial_fma_k(h_k * Wh[k,i])) ----
            float acc = 0.f;
#pragma unroll
            for (int k = 0; k < 128; k += 4) {
                float4 hv = *(const float4*)&h_sh[k];      // warp broadcast
                acc = __fmaf_rn(hv.x, wreg[k + 0], acc);
                acc = __fmaf_rn(hv.y, wreg[k + 1], acc);
                acc = __fmaf_rn(hv.z, wreg[k + 2], acc);
                acc = __fmaf_rn(hv.w, wreg[k + 3], acc);
            }
            float pre = __fadd_rn(xw_cur, acc);
            if (t + 1 < Tsz) xw_cur = xwp[(t + 1) * Dsz + i];   // prefetch

            // ---- a = gelu(pre) (XLA-exact); gp (loose, bf16) ----
            float e;
            float a = xla_gelu(pre, &e);
            a_sh[i] = a;
            float ph = 0.5f * (1.0f + e);
            float gp = ph + pre * 0.39894228040143268f * __expf(-0.5f * pre * pre);
            d_gp[((size_t)t * Bsz + b) * Dsz + i] = __float2bfloat16(gp);
        }
        __syncthreads();    // a_sh ready; h_sh reads of phase A complete

        if (!isA) {
            // ---- sg_i = serial_fma_k(a_k * Wgate[k,i]) ----
            float acc2 = 0.f;
#pragma unroll
            for (int k = 0; k < 128; k += 4) {
                float4 av = *(const float4*)&a_sh[k];      // warp broadcast
                acc2 = __fmaf_rn(av.x, wreg[k + 0], acc2);
                acc2 = __fmaf_rn(av.y, wreg[k + 1], acc2);
                acc2 = __fmaf_rn(av.z, wreg[k + 2], acc2);
                acc2 = __fmaf_rn(av.w, wreg[k + 3], acc2);
            }

            // ---- g = logistic(sg); literal update ----
            float g    = ref_logistic(acc2);
            float hold = h_sh[i];
            float t1 = __fmul_rn(g, hold);
            float t2 = __fsub_rn(1.0f, g);
            float hnew = __fadd_rn(t1, t2);

            size_t r = ((size_t)t * Bsz + b) * Dsz + i;
            float hm1 = __fsub_rn(hold, 1.0f);
            d_g[r] = g;
            d_c[r] = hm1 * g * (1.0f - g);
            yp[t * Dsz + i] = hnew;
            h_sh[i] = hnew;
            if (t == Tsz - 1) hfin[b * Dsz + i] = hnew;
        }
        __syncthreads();    // h_sh stable for next step
    }
}

// ------------------------- K2: jac GEMM (mma.sync bf16) --------------------
// D[m][n] = sum_k GP[tileM*128+m][k] * Vt[tileN*128+n][k]   (NT gemm)
// jac[tb][i=tileN][j] = g*delta(tileN,j) + c * D
#define K2_LDS 136              // smem row stride in elements (128 + 8 pad)

__global__ __launch_bounds__(256, 2) void jac_gemm_kernel(float* __restrict__ jac_out) {
    extern __shared__ __align__(16) __nv_bfloat16 sm[];
    __nv_bfloat16* As = sm;                       // 128 x K2_LDS
    __nv_bfloat16* Bs = sm + 128 * K2_LDS;        // 128 x K2_LDS

    const int tid   = threadIdx.x;
    const int lane  = tid & 31;
    const int wid   = tid >> 5;
    const int wm    = wid & 1;                    // 0..1  (M dir, 64 rows each)
    const int wn    = wid >> 1;                   // 0..3  (N dir, 32 cols each)
    const int tileN = blockIdx.x;                 // i   (0..127)
    const int tileM = blockIdx.y;                 // tb/128 (0..63)

    const uint4* gA = (const uint4*)(d_gp + (size_t)tileM * 128 * Dsz);
    const uint4* gB = (const uint4*)(d_vt + (size_t)tileN * 128 * Dsz);
#pragma unroll
    for (int it = 0; it < 8; it++) {
        int idx   = tid + it * 256;               // 0..2047
        int row   = idx >> 4;
        int chunk = idx & 15;
        *(uint4*)&As[row * K2_LDS + chunk * 8] = gA[idx];
        *(uint4*)&Bs[row * K2_LDS + chunk * 8] = gB[idx];
    }
    __syncthreads();

    const uint32_t as_b = smem_u32(As);
    const uint32_t bs_b = smem_u32(Bs);

    float acc[4][4][4];
#pragma unroll
    for (int mf = 0; mf < 4; mf++)
#pragma unroll
        for (int nf = 0; nf < 4; nf++)
#pragma unroll
            for (int r = 0; r < 4; r++) acc[mf][nf][r] = 0.f;

    const int RM = wm * 64;
    const int CN = wn * 32;

#pragma unroll
    for (int kk = 0; kk < 8; kk++) {
        const int k0 = kk * 16;
        uint32_t a[4][4];
#pragma unroll
        for (int mf = 0; mf < 4; mf++) {
            uint32_t addr = as_b +
                (uint32_t)(((RM + mf * 16 + (lane & 15)) * K2_LDS + k0 + ((lane >> 4) << 3)) * 2);
            asm volatile("ldmatrix.sync.aligned.m8n8.x4.shared.b16 {%0,%1,%2,%3}, [%4];"
                : "=r"(a[mf][0]), "=r"(a[mf][1]), "=r"(a[mf][2]), "=r"(a[mf][3]) : "r"(addr));
        }
        uint32_t bfr[4][2];
#pragma unroll
        for (int nh = 0; nh < 2; nh++) {
            int tile = lane >> 3;
            int rr   = CN + nh * 16 + (lane & 7) + (tile >> 1) * 8;
            int cc   = k0 + (tile & 1) * 8;
            uint32_t addr = bs_b + (uint32_t)((rr * K2_LDS + cc) * 2);
            asm volatile("ldmatrix.sync.aligned.m8n8.x4.shared.b16 {%0,%1,%2,%3}, [%4];"
                : "=r"(bfr[2 * nh][0]), "=r"(bfr[2 * nh][1]),
                  "=r"(bfr[2 * nh + 1][0]), "=r"(bfr[2 * nh + 1][1]) : "r"(addr));
        }
#pragma unroll
        for (int mf = 0; mf < 4; mf++)
#pragma unroll
            for (int nf = 0; nf < 4; nf++) {
                asm volatile(
                    "mma.sync.aligned.m16n8k16.row.col.f32.bf16.bf16.f32 "
                    "{%0,%1,%2,%3}, {%4,%5,%6,%7}, {%8,%9}, {%0,%1,%2,%3};"
                    : "+f"(acc[mf][nf][0]), "+f"(acc[mf][nf][1]),
                      "+f"(acc[mf][nf][2]), "+f"(acc[mf][nf][3])
                    : "r"(a[mf][0]), "r"(a[mf][1]), "r"(a[mf][2]), "r"(a[mf][3]),
                      "r"(bfr[nf][0]), "r"(bfr[nf][1]));
            }
    }

    const int r0 = lane >> 2;            // 0..7
    const int c0 = (lane & 3) * 2;       // 0,2,4,6
#pragma unroll
    for (int mf = 0; mf < 4; mf++) {
        size_t tb0 = (size_t)tileM * 128 + RM + mf * 16 + r0;       // rows r0, r0+8
        float cc0 = d_c[tb0 * Dsz + tileN];
        float gg0 = d_g[tb0 * Dsz + tileN];
        float cc1 = d_c[(tb0 + 8) * Dsz + tileN];
        float gg1 = d_g[(tb0 + 8) * Dsz + tileN];
        float* p0 = jac_out + (tb0 * Dsz + tileN) * Dsz;
        float* p1 = jac_out + ((tb0 + 8) * Dsz + tileN) * Dsz;
#pragma unroll
        for (int nf = 0; nf < 4; nf++) {
            int j = CN + nf * 8 + c0;
            float2 v0, v1;
            v0.x = cc0 * acc[mf][nf][0];
            v0.y = cc0 * acc[mf][nf][1];
            v1.x = cc1 * acc[mf][nf][2];
            v1.y = cc1 * acc[mf][nf][3];
            if (j == tileN)     { v0.x += gg0; v1.x += gg1; }
            if (j + 1 == tileN) { v0.y += gg0; v1.y += gg1; }
            *(float2*)(p0 + j) = v0;
            *(float2*)(p1 + j) = v1;
        }
    }
}

// ------------------------- K3a: final-step recompute -----------------------
__global__ void final_step_kernel(const float* __restrict__ Wh,
                                  const float* __restrict__ Wgate,
                                  const float* __restrict__ hfin) {
    __shared__ __align__(16) float hs[Dsz];
    __shared__ __align__(16) float as_[Dsz];
    int b = blockIdx.x, i = threadIdx.x;
    hs[i] = hfin[b * Dsz + i];
    __syncthreads();
    float acc = 0.f;
#pragma unroll
    for (int j = 0; j < Dsz; j++) acc = __fmaf_rn(hs[j], Wh[j * Dsz + i], acc);
    float pre = __fadd_rn(d_xw[((size_t)b * Tsz + (Tsz - 1)) * Dsz + i], acc);
    float e;
    float a = xla_gelu(pre, &e);
    float ph = 0.5f * (1.0f + e);
    d_gpf[b * Dsz + i] = ph + pre * 0.39894228040143268f * __expf(-0.5f * pre * pre);
    as_[i] = a;
    __syncthreads();
    float sg = 0.f;
#pragma unroll
    for (int k = 0; k < Dsz; k++) sg = __fmaf_rn(as_[k], Wgate[k * Dsz + i], sg);
    float g = ref_logistic(sg);
    d_cf[b * Dsz + i] = __fsub_rn(hs[i], 1.0f) * g * (1.0f - g);
}

// ------------------------- K3b: dh_dWh -------------------------------------
// dwh[b,i,p,q] = cf[b,i] * hf[b,p] * gpf[b,q] * Wgate[q,i]
__global__ void dwh_kernel(const float* __restrict__ Wgate,
                           const float* __restrict__ hfin,
                           float* __restrict__ dwh) {
    __shared__ __align__(16) float hs[Dsz];
    int i = blockIdx.x, b = blockIdx.y, q = threadIdx.x;
    float w = Wgate[q * Dsz + i] * d_gpf[b * Dsz + q];
    hs[q] = hfin[b * Dsz + q];
    float cw = d_cf[(size_t)b * Dsz + i] * w;
    __syncthreads();
    float* op = dwh + ((size_t)b * Dsz + i) * Dsz * Dsz + q;
#pragma unroll 4
    for (int p = 0; p < Dsz; p++) op[(size_t)p * Dsz] = cw * hs[p];
}

// ------------------------- launch ------------------------------------------
extern "C" void kernel_launch(void* const* d_in, const int* in_sizes, int n_in,
                              void* d_out, int out_size) {
    const float* x     = (const float*)d_in[0];
    const float* h0    = (const float*)d_in[1];
    const float* Wx    = (const float*)d_in[2];
    const float* Wgate = (const float*)d_in[3];
    const float* Wh    = (const float*)d_in[4];

    float* out  = (float*)d_out;
    float* hfin = out;                                   // 4096
    float* y    = out + 4096;                            // 1,048,576
    float* jac  = out + 4096 + (size_t)Bsz * Tsz * Dsz;  // 134,217,728
    float* dwh  = jac + (size_t)Tsz * Bsz * Dsz * Dsz;   // 67,108,864

    const int K2_SMEM  = 2 * 128 * K2_LDS * 2;           // 69632 B
    cudaFuncSetAttribute(jac_gemm_kernel,
                         cudaFuncAttributeMaxDynamicSharedMemorySize, K2_SMEM);

    xw_kernel<<<BT, Dsz>>>(x, Wx);
    build_vt_kernel<<<NN, Dsz>>>(Wh, Wgate);
    rnn_kernel<<<Bsz, 256>>>(h0, Wh, Wgate, y, hfin);
    jac_gemm_kernel<<<dim3(Dsz, BT / 128), 256, K2_SMEM>>>(jac);
    final_step_kernel<<<Bsz, Dsz>>>(Wh, Wgate, hfin);
    dwh_kernel<<<dim3(Dsz, Bsz), Dsz>>>(Wgate, hfin, dwh);
}